// round 15
// baseline (speedup 1.0000x reference)
#include <cuda_runtime.h>
#include <cuda_fp16.h>
#include <cstdint>

// Problem constants
#define KC  8192          // number of codes
#define DD  256           // embedding / channel dim
#define NR  16384         // B*H*W rows
#define HW  1024          // H*W
#define CHW (DD * HW)     // per-batch stride in z / out

#define CAPM    32        // candidate list capacity per row (== warp size)
#define MARGIN  4e-4f     // >= ~7x worst-case fp16 score error (~6e-5)

#define ESCALE  8192.0f   // codebook pre-scale (keeps fp16 normal range)
#define SINV    (-2.0f / ESCALE)

// Scratch (static device memory)
__device__ float g_codebook[KC * DD];        // emb @ proj_w^T fp32
__device__ float g_zf[NR * DD];              // z transposed [N][D] fp32
__device__ float g_zn[NR];                   // ||z_n||^2 (fp32 chain)
__device__ int   g_cand[NR * CAPM];          // candidate indices
__device__ int   g_cand_cnt[NR];             // count (>CAPM = overflow)
__device__ int   g_minidx[NR];
__device__ float g_partials[512];

// half2 operands, d-pair-major: [dp 0..127][index]; codebook scaled by ESCALE
__device__ __align__(16) __half2 g_ch2[128 * KC];
__device__ __align__(16) __half2 g_zh2[128 * NR];

// ---------------------------------------------------------------------------
// Kernel 1: codebook = emb @ proj^T (exact fp32 sequential-j chain) +
// fused scaled-half2 transposed pack into g_ch2[dp][k].
// ---------------------------------------------------------------------------
__global__ void codebook_gemm(const float* __restrict__ emb,
                              const float* __restrict__ pw) {
    __shared__ float As[16 * 65];
    __shared__ float Bs[16 * 65];
    const int tid = threadIdx.x;
    const int tx = tid & 15, ty = tid >> 4;
    const int k0 = blockIdx.y * 64;
    const int d0 = blockIdx.x * 64;
    const int rl = tid >> 2;
    const int j4 = (tid & 3) << 2;

    float acc[4][4];
#pragma unroll
    for (int u = 0; u < 4; u++)
#pragma unroll
        for (int v = 0; v < 4; v++) acc[u][v] = 0.f;

    for (int j0 = 0; j0 < DD; j0 += 16) {
        float4 va = *(const float4*)&emb[(k0 + rl) * DD + j0 + j4];
        float4 vb = *(const float4*)&pw[(d0 + rl) * DD + j0 + j4];
        As[(j4 + 0) * 65 + rl] = va.x;  As[(j4 + 1) * 65 + rl] = va.y;
        As[(j4 + 2) * 65 + rl] = va.z;  As[(j4 + 3) * 65 + rl] = va.w;
        Bs[(j4 + 0) * 65 + rl] = vb.x;  Bs[(j4 + 1) * 65 + rl] = vb.y;
        Bs[(j4 + 2) * 65 + rl] = vb.z;  Bs[(j4 + 3) * 65 + rl] = vb.w;
        __syncthreads();
#pragma unroll
        for (int jj = 0; jj < 16; jj++) {
            const float* ap = &As[jj * 65 + ty * 4];
            const float* bp = &Bs[jj * 65 + tx * 4];
            float a0 = ap[0], a1 = ap[1], a2 = ap[2], a3 = ap[3];
            float b0 = bp[0], b1 = bp[1], b2 = bp[2], b3 = bp[3];
            acc[0][0] = fmaf(a0, b0, acc[0][0]); acc[0][1] = fmaf(a0, b1, acc[0][1]);
            acc[0][2] = fmaf(a0, b2, acc[0][2]); acc[0][3] = fmaf(a0, b3, acc[0][3]);
            acc[1][0] = fmaf(a1, b0, acc[1][0]); acc[1][1] = fmaf(a1, b1, acc[1][1]);
            acc[1][2] = fmaf(a1, b2, acc[1][2]); acc[1][3] = fmaf(a1, b3, acc[1][3]);
            acc[2][0] = fmaf(a2, b0, acc[2][0]); acc[2][1] = fmaf(a2, b1, acc[2][1]);
            acc[2][2] = fmaf(a2, b2, acc[2][2]); acc[2][3] = fmaf(a2, b3, acc[2][3]);
            acc[3][0] = fmaf(a3, b0, acc[3][0]); acc[3][1] = fmaf(a3, b1, acc[3][1]);
            acc[3][2] = fmaf(a3, b2, acc[3][2]); acc[3][3] = fmaf(a3, b3, acc[3][3]);
        }
        __syncthreads();
    }
#pragma unroll
    for (int u = 0; u < 4; u++) {
        int k = k0 + ty * 4 + u;
        float4 w = make_float4(acc[u][0], acc[u][1], acc[u][2], acc[u][3]);
        *(float4*)&g_codebook[k * DD + d0 + tx * 4] = w;
        int dp0 = (d0 + tx * 4) >> 1;
        g_ch2[(dp0 + 0) * KC + k] =
            __floats2half2_rn(acc[u][0] * ESCALE, acc[u][1] * ESCALE);
        g_ch2[(dp0 + 1) * KC + k] =
            __floats2half2_rn(acc[u][2] * ESCALE, acc[u][3] * ESCALE);
    }
}

// ---------------------------------------------------------------------------
// Kernel 2: z transpose -> g_zf [N][D] fp32, zn per row (sequential chain),
// fused half2 pair pack into g_zh2[dp][n].
// ---------------------------------------------------------------------------
__global__ void z_prep(const float* __restrict__ z) {
    __shared__ float Zs[256 * 33];
    const int tid = threadIdx.x;
    const int n0 = blockIdx.x * 32;
    const int b = n0 >> 10, hw0 = n0 & 1023;
    const float* zb = z + b * CHW + hw0;

    for (int e = tid; e < 32 * DD; e += 256) {
        int d = e >> 5, m = e & 31;
        Zs[d * 33 + m] = zb[d * HW + m];
    }
    __syncthreads();
    // fp32 transposed copy for rescue
    for (int idx = tid; idx < 32 * DD; idx += 256) {
        int nl = idx >> 8, d = idx & 255;
        g_zf[(n0 + nl) * DD + d] = Zs[d * 33 + nl];
    }
    // half2 pair pack (nl fastest -> coalesced stores)
    for (int idx = tid; idx < 32 * 128; idx += 256) {
        int nl = idx & 31, dp = idx >> 5;
        g_zh2[dp * NR + n0 + nl] =
            __floats2half2_rn(Zs[(2 * dp) * 33 + nl], Zs[(2 * dp + 1) * 33 + nl]);
    }
    if (tid < 32) {
        float s = 0.f;
#pragma unroll 8
        for (int d = 0; d < DD; d++) { float v = Zs[d * 33 + tid]; s = fmaf(v, v, s); }
        g_zn[n0 + tid] = s;
    }
}

// ---------------------------------------------------------------------------
// Kernel 3: HFMA2 distance GEMM + two-phase margin candidate collect.
// (Unchanged from R13 — measured at the HFMA2 pipe wall.)
// ---------------------------------------------------------------------------
#define ZH_OFF    0
#define ES_OFF    32768
#define LIST_OFF  65536
#define CNT_OFF   (LIST_OFF + 64 * CAPM * 4)
#define SMEM_H2   (CNT_OFF + 64 * 4)

__global__ __launch_bounds__(256, 2)
void argmin_h2(void) {
    extern __shared__ char sm[];
    __half2* Zh = (__half2*)(sm + ZH_OFF);   // [128 dp][64 rows]
    __half2* Es = (__half2*)(sm + ES_OFF);   // [128 dp][64 codes]
    int* slist  = (int*)(sm + LIST_OFF);
    int* scnt   = (int*)(sm + CNT_OFF);

    const int tid = threadIdx.x;
    const int tx = tid & 15, ty = tid >> 4;  // 16 codes x 16 row-groups
    const int n0 = blockIdx.x * 64;

    if (tid < 64) scnt[tid] = 0;

    // Load resident z tile: Zh[dp][r]  (uint4 = 4 half2)
    for (int i = tid; i < 2048; i += 256) {
        int dp = i >> 4, seg = i & 15;
        *(uint4*)&Zh[dp * 64 + seg * 4] =
            *(const uint4*)&g_zh2[dp * NR + n0 + seg * 4];
    }
    // Prefetch codebook chunk 0 into registers (8 x 16B per thread)
    uint4 pre[8];
#pragma unroll
    for (int j = 0; j < 8; j++) {
        int idx = tid * 8 + j;
        int dp = idx >> 4, seg = idx & 15;
        pre[j] = *(const uint4*)&g_ch2[dp * KC + seg * 4];
    }

    float zn[4], rm[4];
#pragma unroll
    for (int r = 0; r < 4; r++) {
        zn[r] = g_zn[n0 + ty * 4 + r];
        rm[r] = 3.4e38f;
    }

    for (int it = 0; it < 128; it++) {
        // store prefetched chunk
#pragma unroll
        for (int j = 0; j < 8; j++) {
            int idx = tid * 8 + j;
            int dp = idx >> 4, seg = idx & 15;
            *(uint4*)&Es[dp * 64 + seg * 4] = pre[j];
        }
        __syncthreads();

        // prefetch next chunk while computing
        uint4 nxt[8];
        if (it + 1 < 128) {
            const int kn = (it + 1) * 64;
#pragma unroll
            for (int j = 0; j < 8; j++) {
                int idx = tid * 8 + j;
                int dp = idx >> 4, seg = idx & 15;
                nxt[j] = *(const uint4*)&g_ch2[dp * KC + kn + seg * 4];
            }
        }

        const __half2* Zp = Zh + ty * 4;
        const __half2* Ep = Es + tx * 4;

        float c32[4][4];
#pragma unroll
        for (int r = 0; r < 4; r++)
#pragma unroll
            for (int v = 0; v < 4; v++) c32[r][v] = 0.f;

#pragma unroll 1
        for (int o = 0; o < 4; o++) {           // 4 blocks of 32 d-pairs
            __half2 h[4][4];
            const __half2 hz = __floats2half2_rn(0.f, 0.f);
#pragma unroll
            for (int r = 0; r < 4; r++)
#pragma unroll
                for (int v = 0; v < 4; v++) h[r][v] = hz;
#pragma unroll
            for (int d = 0; d < 32; d++) {
                int dp = o * 32 + d;
                float4 zv = *(const float4*)(Zp + dp * 64);
                float4 ev = *(const float4*)(Ep + dp * 64);
                __half2 z0 = *(__half2*)&zv.x, z1 = *(__half2*)&zv.y;
                __half2 z2 = *(__half2*)&zv.z, z3 = *(__half2*)&zv.w;
                __half2 e0 = *(__half2*)&ev.x, e1 = *(__half2*)&ev.y;
                __half2 e2 = *(__half2*)&ev.z, e3 = *(__half2*)&ev.w;
                h[0][0] = __hfma2(z0, e0, h[0][0]); h[0][1] = __hfma2(z0, e1, h[0][1]);
                h[0][2] = __hfma2(z0, e2, h[0][2]); h[0][3] = __hfma2(z0, e3, h[0][3]);
                h[1][0] = __hfma2(z1, e0, h[1][0]); h[1][1] = __hfma2(z1, e1, h[1][1]);
                h[1][2] = __hfma2(z1, e2, h[1][2]); h[1][3] = __hfma2(z1, e3, h[1][3]);
                h[2][0] = __hfma2(z2, e0, h[2][0]); h[2][1] = __hfma2(z2, e1, h[2][1]);
                h[2][2] = __hfma2(z2, e2, h[2][2]); h[2][3] = __hfma2(z2, e3, h[2][3]);
                h[3][0] = __hfma2(z3, e0, h[3][0]); h[3][1] = __hfma2(z3, e1, h[3][1]);
                h[3][2] = __hfma2(z3, e2, h[3][2]); h[3][3] = __hfma2(z3, e3, h[3][3]);
            }
            // fp32 merge
#pragma unroll
            for (int r = 0; r < 4; r++)
#pragma unroll
                for (int v = 0; v < 4; v++)
                    c32[r][v] += __low2float(h[r][v]) + __high2float(h[r][v]);
        }

        // ---- two-phase epilogue ----
        const int kb = it * 64 + tx * 4;
        float sv[4][4];
#pragma unroll
        for (int r = 0; r < 4; r++) {
            float cmin = 3.4e38f;
#pragma unroll
            for (int v = 0; v < 4; v++) {
                sv[r][v] = fmaf(c32[r][v], SINV, zn[r]);
                cmin = fminf(cmin, sv[r][v]);
            }
#pragma unroll
            for (int o = 8; o; o >>= 1)
                cmin = fminf(cmin, __shfl_xor_sync(0xffffffffu, cmin, o));
            rm[r] = fminf(rm[r], cmin);
        }
#pragma unroll
        for (int r = 0; r < 4; r++) {
            const int row = ty * 4 + r;
            const float thr = rm[r] + MARGIN;
#pragma unroll
            for (int v = 0; v < 4; v++) {
                if (sv[r][v] < thr) {
                    int sl = atomicAdd(&scnt[row], 1);
                    if (sl < CAPM) slist[row * CAPM + sl] = kb + v;
                }
            }
        }

#pragma unroll
        for (int j = 0; j < 8; j++) pre[j] = nxt[j];
        __syncthreads();
    }

    if (tid < 64) {
        int cnt = scnt[tid];
        int n = n0 + tid;
        g_cand_cnt[n] = (cnt > CAPM) ? (CAPM + 1) : cnt;
        int m = (cnt < CAPM) ? cnt : CAPM;
        for (int j = 0; j < m; j++) g_cand[n * CAPM + j] = slist[tid * CAPM + j];
    }
}

// ---------------------------------------------------------------------------
// Kernel 4: exact rescue, WARP-PER-ROW. Block = 8 warps = 8 rows; lane j =
// candidate j (CAPM == 32). zrows staged in smem (warp-broadcast reads).
// Same bit-exact sequential fp32 chain + lexicographic (val, idx) min,
// reduced via shfl (no block syncs in the reduce).
// ---------------------------------------------------------------------------
__global__ __launch_bounds__(256)
void rescue_kernel(float* __restrict__ idxf) {
    __shared__ __align__(16) float zs[8][DD];
    const int tid = threadIdx.x;
    const int w = tid >> 5, lane = tid & 31;
    const int n0 = blockIdx.x * 8;
    const int n = n0 + w;

    // cooperative zrow staging: 8 rows x 64 float4
    for (int i = tid; i < 8 * 64; i += 256) {
        int r = i >> 6, seg = i & 63;
        *(float4*)&zs[r][seg * 4] = *(const float4*)&g_zf[(n0 + r) * DD + seg * 4];
    }
    __syncthreads();

    const float zn = g_zn[n];
    const int cnt = g_cand_cnt[n];
    const float4* zr = (const float4*)zs[w];

    float bv = 3.4e38f; int bi = 0x7FFFFFFF;
    if (cnt > CAPM) {
        // rare overflow: full scan distributed over 32 lanes
        for (int k = lane; k < KC; k += 32) {
            float acc = 0.f;
            const float4* cb = (const float4*)&g_codebook[k * DD];
#pragma unroll 4
            for (int d4 = 0; d4 < 64; d4++) {
                float4 cc = cb[d4];
                float4 zv = zr[d4];
                acc = fmaf(zv.x, cc.x, acc); acc = fmaf(zv.y, cc.y, acc);
                acc = fmaf(zv.z, cc.z, acc); acc = fmaf(zv.w, cc.w, acc);
            }
            float s = fmaf(-2.f, acc, zn);
            if (s < bv || (s == bv && k < bi)) { bv = s; bi = k; }
        }
    } else if (lane < cnt) {
        int k = g_cand[n * CAPM + lane];
        float acc = 0.f;
        const float4* cb = (const float4*)&g_codebook[k * DD];
#pragma unroll 4
        for (int d4 = 0; d4 < 64; d4++) {
            float4 cc = cb[d4];
            float4 zv = zr[d4];
            acc = fmaf(zv.x, cc.x, acc); acc = fmaf(zv.y, cc.y, acc);
            acc = fmaf(zv.z, cc.z, acc); acc = fmaf(zv.w, cc.w, acc);
        }
        bv = fmaf(-2.f, acc, zn);
        bi = k;
    }

    // warp lexicographic (val, idx) min
#pragma unroll
    for (int o = 16; o; o >>= 1) {
        float v = __shfl_xor_sync(0xffffffffu, bv, o);
        int i2 = __shfl_xor_sync(0xffffffffu, bi, o);
        if (v < bv || (v == bv && i2 < bi)) { bv = v; bi = i2; }
    }
    if (lane == 0) {
        g_minidx[n] = bi;
        if (idxf) idxf[n] = (float)bi;
    }
}

// ---------------------------------------------------------------------------
// Kernel 5: gather + straight-through output + squared error partials.
// out = fl(zt + fl(zq - zt)) exactly as the reference.
// ---------------------------------------------------------------------------
__global__ void gather_out(const float* __restrict__ z, float* __restrict__ out) {
    __shared__ float s[256 * 33];
    const int tid = threadIdx.x;
    const int n0 = blockIdx.x * 32;
    const int b = n0 >> 10, hw0 = n0 & 1023;

#pragma unroll 1
    for (int nl = 0; nl < 32; nl++) {
        int ci = g_minidx[n0 + nl];
        s[tid * 33 + nl] = g_codebook[ci * DD + tid];
    }
    __syncthreads();

    float local = 0.f;
    const float* zb = z + b * CHW + hw0;
    float* ob = out + b * CHW + hw0;
    for (int e = tid; e < 32 * DD; e += 256) {
        int c = e >> 5, hl = e & 31;
        float q  = s[c * 33 + hl];
        float zv = zb[c * HW + hl];
        float d  = q - zv;
        ob[c * HW + hl] = zv + d;
        local = fmaf(d, d, local);
    }
    __syncthreads();
    float* red = s;
    red[tid] = local;
    __syncthreads();
    for (int o = 128; o; o >>= 1) {
        if (tid < o) red[tid] += red[tid + o];
        __syncthreads();
    }
    if (tid == 0) g_partials[blockIdx.x] = red[0];
}

// ---------------------------------------------------------------------------
// Kernel 6: final reduction + loss scalars
// ---------------------------------------------------------------------------
__global__ void finalize_kernel(float* __restrict__ outp, int has_scalars) {
    __shared__ float red[512];
    const int tid = threadIdx.x;
    red[tid] = g_partials[tid];
    __syncthreads();
    for (int o = 256; o; o >>= 1) {
        if (tid < o) red[tid] += red[tid + o];
        __syncthreads();
    }
    if (tid == 0 && has_scalars) {
        float mse = red[0] * (1.0f / 4194304.0f);
        float cl  = 0.25f * mse;
        float bl  = mse;
        outp[4194304] = cl + bl;
        outp[4194305] = cl;
        outp[4194306] = bl;
    }
}

// ---------------------------------------------------------------------------
extern "C" void kernel_launch(void* const* d_in, const int* in_sizes, int n_in,
                              void* d_out, int out_size) {
    const float* z   = (const float*)d_in[0];   // [16,256,32,32]
    const float* emb = (const float*)d_in[1];   // [8192,256]
    const float* pw  = (const float*)d_in[2];   // [256,256]
    float* out = (float*)d_out;

    cudaFuncSetAttribute(argmin_h2,
                         cudaFuncAttributeMaxDynamicSharedMemorySize, SMEM_H2);

    codebook_gemm<<<dim3(4, 128), 256>>>(emb, pw);
    z_prep<<<512, 256>>>(z);

    float* idxf = nullptr;
    if (out_size >= 4194307 + NR) idxf = out + 4194307;

    argmin_h2<<<256, 256, SMEM_H2>>>();
    rescue_kernel<<<NR / 8, 256>>>(idxf);
    gather_out<<<512, 256>>>(z, out);
    finalize_kernel<<<1, 512>>>(out, (out_size >= 4194307) ? 1 : 0);
}

// round 17
// speedup vs baseline: 2.1013x; 2.1013x over previous
#include <cuda_runtime.h>
#include <cuda_fp16.h>
#include <cstdint>

// Problem constants
#define KC  8192          // number of codes
#define DD  256           // embedding / channel dim
#define NR  16384         // B*H*W rows
#define HW  1024          // H*W
#define CHW (DD * HW)     // per-batch stride in z / out

#define CAPM    32        // candidate list capacity per row (== warp size)
#define MARGIN  4e-4f     // >= ~7x worst-case fp16 score error (~6e-5)

#define ESCALE  8192.0f   // codebook pre-scale (keeps fp16 normal range)
#define SINV    (-2.0f / ESCALE)

// Scratch (static device memory)
__device__ float g_codebook[KC * DD];        // emb @ proj_w^T fp32
__device__ float g_zf[NR * DD];              // z transposed [N][D] fp32
__device__ float g_zn[NR];                   // ||z_n||^2 (fp32 chain)
__device__ int   g_cand[NR * CAPM];          // candidate indices
__device__ int   g_cand_cnt[NR];             // count (>CAPM = overflow)
__device__ int   g_minidx[NR];
__device__ float g_partials[512];

// half2 operands, d-pair-major: [dp 0..127][index]; codebook scaled by ESCALE
__device__ __align__(16) __half2 g_ch2[128 * KC];
__device__ __align__(16) __half2 g_zh2[128 * NR];

// ---------------------------------------------------------------------------
// Kernel 1: codebook = emb @ proj^T (exact fp32 sequential-j chain) +
// fused scaled-half2 transposed pack into g_ch2[dp][k].
// ---------------------------------------------------------------------------
__global__ void codebook_gemm(const float* __restrict__ emb,
                              const float* __restrict__ pw) {
    __shared__ float As[16 * 65];
    __shared__ float Bs[16 * 65];
    const int tid = threadIdx.x;
    const int tx = tid & 15, ty = tid >> 4;
    const int k0 = blockIdx.y * 64;
    const int d0 = blockIdx.x * 64;
    const int rl = tid >> 2;
    const int j4 = (tid & 3) << 2;

    float acc[4][4];
#pragma unroll
    for (int u = 0; u < 4; u++)
#pragma unroll
        for (int v = 0; v < 4; v++) acc[u][v] = 0.f;

    for (int j0 = 0; j0 < DD; j0 += 16) {
        float4 va = *(const float4*)&emb[(k0 + rl) * DD + j0 + j4];
        float4 vb = *(const float4*)&pw[(d0 + rl) * DD + j0 + j4];
        As[(j4 + 0) * 65 + rl] = va.x;  As[(j4 + 1) * 65 + rl] = va.y;
        As[(j4 + 2) * 65 + rl] = va.z;  As[(j4 + 3) * 65 + rl] = va.w;
        Bs[(j4 + 0) * 65 + rl] = vb.x;  Bs[(j4 + 1) * 65 + rl] = vb.y;
        Bs[(j4 + 2) * 65 + rl] = vb.z;  Bs[(j4 + 3) * 65 + rl] = vb.w;
        __syncthreads();
#pragma unroll
        for (int jj = 0; jj < 16; jj++) {
            const float* ap = &As[jj * 65 + ty * 4];
            const float* bp = &Bs[jj * 65 + tx * 4];
            float a0 = ap[0], a1 = ap[1], a2 = ap[2], a3 = ap[3];
            float b0 = bp[0], b1 = bp[1], b2 = bp[2], b3 = bp[3];
            acc[0][0] = fmaf(a0, b0, acc[0][0]); acc[0][1] = fmaf(a0, b1, acc[0][1]);
            acc[0][2] = fmaf(a0, b2, acc[0][2]); acc[0][3] = fmaf(a0, b3, acc[0][3]);
            acc[1][0] = fmaf(a1, b0, acc[1][0]); acc[1][1] = fmaf(a1, b1, acc[1][1]);
            acc[1][2] = fmaf(a1, b2, acc[1][2]); acc[1][3] = fmaf(a1, b3, acc[1][3]);
            acc[2][0] = fmaf(a2, b0, acc[2][0]); acc[2][1] = fmaf(a2, b1, acc[2][1]);
            acc[2][2] = fmaf(a2, b2, acc[2][2]); acc[2][3] = fmaf(a2, b3, acc[2][3]);
            acc[3][0] = fmaf(a3, b0, acc[3][0]); acc[3][1] = fmaf(a3, b1, acc[3][1]);
            acc[3][2] = fmaf(a3, b2, acc[3][2]); acc[3][3] = fmaf(a3, b3, acc[3][3]);
        }
        __syncthreads();
    }
#pragma unroll
    for (int u = 0; u < 4; u++) {
        int k = k0 + ty * 4 + u;
        float4 w = make_float4(acc[u][0], acc[u][1], acc[u][2], acc[u][3]);
        *(float4*)&g_codebook[k * DD + d0 + tx * 4] = w;
        int dp0 = (d0 + tx * 4) >> 1;
        g_ch2[(dp0 + 0) * KC + k] =
            __floats2half2_rn(acc[u][0] * ESCALE, acc[u][1] * ESCALE);
        g_ch2[(dp0 + 1) * KC + k] =
            __floats2half2_rn(acc[u][2] * ESCALE, acc[u][3] * ESCALE);
    }
}

// ---------------------------------------------------------------------------
// Kernel 2: z transpose -> g_zf [N][D] fp32, zn per row (sequential chain),
// fused half2 pair pack into g_zh2[dp][n].
// ---------------------------------------------------------------------------
__global__ void z_prep(const float* __restrict__ z) {
    __shared__ float Zs[256 * 33];
    const int tid = threadIdx.x;
    const int n0 = blockIdx.x * 32;
    const int b = n0 >> 10, hw0 = n0 & 1023;
    const float* zb = z + b * CHW + hw0;

    for (int e = tid; e < 32 * DD; e += 256) {
        int d = e >> 5, m = e & 31;
        Zs[d * 33 + m] = zb[d * HW + m];
    }
    __syncthreads();
    // fp32 transposed copy for rescue
    for (int idx = tid; idx < 32 * DD; idx += 256) {
        int nl = idx >> 8, d = idx & 255;
        g_zf[(n0 + nl) * DD + d] = Zs[d * 33 + nl];
    }
    // half2 pair pack (nl fastest -> coalesced stores)
    for (int idx = tid; idx < 32 * 128; idx += 256) {
        int nl = idx & 31, dp = idx >> 5;
        g_zh2[dp * NR + n0 + nl] =
            __floats2half2_rn(Zs[(2 * dp) * 33 + nl], Zs[(2 * dp + 1) * 33 + nl]);
    }
    if (tid < 32) {
        float s = 0.f;
#pragma unroll 8
        for (int d = 0; d < DD; d++) { float v = Zs[d * 33 + tid]; s = fmaf(v, v, s); }
        g_zn[n0 + tid] = s;
    }
}

// ---------------------------------------------------------------------------
// Kernel 3: HFMA2 distance GEMM + two-phase margin candidate collect.
// Block = 128 rows resident (Zh 64KB = 4096 uint4); 64 chunks of 128 codes,
// Es double-buffered (2 x 64KB). 512 threads = 16 row-groups x 32 code-
// groups; thread tile 8 rows x 4 codes (1.5 B smem per HFMA2 -> fma-bound).
// NOTE: uint4 = 4 half2 (16B). Tile = 4096 uint4; fills use dp=i>>5,
// seg=i&31 (32 segs x 4 elements = 128). This was the R16 crash: fills
// used 8-half2 strides, leaving half of each tile as garbage -> NaN
// scores -> empty candidate lists -> sentinel index -> OOB in gather.
// ---------------------------------------------------------------------------
#define NRB   128                       // rows per block
#define ZH_OFF    0                     // 64KB: [128 dp][128 rows] half2
#define ES_OFF    65536                 // 2 x 64KB: [128 dp][128 codes] half2
#define LIST_OFF  (65536 + 131072)      // 196608
#define CNT_OFF   (LIST_OFF + NRB * CAPM * 4)
#define SMEM_H2   (CNT_OFF + NRB * 4)   // 213504 B

__global__ __launch_bounds__(512, 1)
void argmin_h2(void) {
    extern __shared__ char sm[];
    __half2* Zh = (__half2*)(sm + ZH_OFF);
    int* slist  = (int*)(sm + LIST_OFF);
    int* scnt   = (int*)(sm + CNT_OFF);

    const int tid = threadIdx.x;
    const int rg = tid >> 5;             // row group 0..15 (8 rows each)
    const int cg = tid & 31;             // code group 0..31 (4 codes each)
    const int n0 = blockIdx.x * NRB;

    if (tid < NRB) scnt[tid] = 0;

    // Fill resident z tile: 4096 uint4; uint4 = 4 half2 = 4 rows
    for (int i = tid; i < 4096; i += 512) {
        int dp = i >> 5, seg = i & 31;
        ((uint4*)Zh)[i] = *(const uint4*)&g_zh2[dp * NR + n0 + seg * 4];
    }
    // Fill Es buffer 0 with chunk 0: 4096 uint4; uint4 = 4 codes
    for (int i = tid; i < 4096; i += 512) {
        int dp = i >> 5, seg = i & 31;
        ((uint4*)(sm + ES_OFF))[i] = *(const uint4*)&g_ch2[dp * KC + seg * 4];
    }
    __syncthreads();

    float zn[8], rm[8];
#pragma unroll
    for (int r = 0; r < 8; r++) {
        zn[r] = g_zn[n0 + rg * 8 + r];
        rm[r] = 3.4e38f;
    }

    for (int it = 0; it < 64; it++) {
        // fill NEXT buffer (its last reader synced at the end of it-1)
        if (it + 1 < 64) {
            const int kn = (it + 1) * 128;
            uint4* nb = (uint4*)(sm + ES_OFF + (((it + 1) & 1) << 16));
#pragma unroll
            for (int j = 0; j < 8; j++) {
                int i = tid + j * 512;
                int dp = i >> 5, seg = i & 31;
                nb[i] = *(const uint4*)&g_ch2[dp * KC + kn + seg * 4];
            }
        }

        const __half2* Zp = Zh + rg * 8;
        const __half2* Ep = (const __half2*)(sm + ES_OFF + ((it & 1) << 16)) + cg * 4;

        float c32[8][4];
#pragma unroll
        for (int r = 0; r < 8; r++)
#pragma unroll
            for (int v = 0; v < 4; v++) c32[r][v] = 0.f;

#pragma unroll 1
        for (int o = 0; o < 4; o++) {           // 4 blocks of 32 d-pairs
            __half2 h[8][4];
            const __half2 hz = __floats2half2_rn(0.f, 0.f);
#pragma unroll
            for (int r = 0; r < 8; r++)
#pragma unroll
                for (int v = 0; v < 4; v++) h[r][v] = hz;
#pragma unroll 8
            for (int d = 0; d < 32; d++) {
                int dp = o * 32 + d;
                float4 za = *(const float4*)(Zp + dp * 128);      // rows 0..3
                float4 zb = *(const float4*)(Zp + dp * 128 + 4);  // rows 4..7
                float4 ev = *(const float4*)(Ep + dp * 128);      // 4 codes
                __half2 z0 = *(__half2*)&za.x, z1 = *(__half2*)&za.y;
                __half2 z2 = *(__half2*)&za.z, z3 = *(__half2*)&za.w;
                __half2 z4 = *(__half2*)&zb.x, z5 = *(__half2*)&zb.y;
                __half2 z6 = *(__half2*)&zb.z, z7 = *(__half2*)&zb.w;
                __half2 e0 = *(__half2*)&ev.x, e1 = *(__half2*)&ev.y;
                __half2 e2 = *(__half2*)&ev.z, e3 = *(__half2*)&ev.w;
                h[0][0] = __hfma2(z0, e0, h[0][0]); h[0][1] = __hfma2(z0, e1, h[0][1]);
                h[0][2] = __hfma2(z0, e2, h[0][2]); h[0][3] = __hfma2(z0, e3, h[0][3]);
                h[1][0] = __hfma2(z1, e0, h[1][0]); h[1][1] = __hfma2(z1, e1, h[1][1]);
                h[1][2] = __hfma2(z1, e2, h[1][2]); h[1][3] = __hfma2(z1, e3, h[1][3]);
                h[2][0] = __hfma2(z2, e0, h[2][0]); h[2][1] = __hfma2(z2, e1, h[2][1]);
                h[2][2] = __hfma2(z2, e2, h[2][2]); h[2][3] = __hfma2(z2, e3, h[2][3]);
                h[3][0] = __hfma2(z3, e0, h[3][0]); h[3][1] = __hfma2(z3, e1, h[3][1]);
                h[3][2] = __hfma2(z3, e2, h[3][2]); h[3][3] = __hfma2(z3, e3, h[3][3]);
                h[4][0] = __hfma2(z4, e0, h[4][0]); h[4][1] = __hfma2(z4, e1, h[4][1]);
                h[4][2] = __hfma2(z4, e2, h[4][2]); h[4][3] = __hfma2(z4, e3, h[4][3]);
                h[5][0] = __hfma2(z5, e0, h[5][0]); h[5][1] = __hfma2(z5, e1, h[5][1]);
                h[5][2] = __hfma2(z5, e2, h[5][2]); h[5][3] = __hfma2(z5, e3, h[5][3]);
                h[6][0] = __hfma2(z6, e0, h[6][0]); h[6][1] = __hfma2(z6, e1, h[6][1]);
                h[6][2] = __hfma2(z6, e2, h[6][2]); h[6][3] = __hfma2(z6, e3, h[6][3]);
                h[7][0] = __hfma2(z7, e0, h[7][0]); h[7][1] = __hfma2(z7, e1, h[7][1]);
                h[7][2] = __hfma2(z7, e2, h[7][2]); h[7][3] = __hfma2(z7, e3, h[7][3]);
            }
            // fp32 merge
#pragma unroll
            for (int r = 0; r < 8; r++)
#pragma unroll
                for (int v = 0; v < 4; v++)
                    c32[r][v] += __low2float(h[r][v]) + __high2float(h[r][v]);
        }

        // ---- two-phase epilogue (full-warp row-min; a row's 32 scorers
        //      are exactly the 32 lanes of one warp) ----
        const int kb = it * 128 + cg * 4;
        float sv[8][4];
#pragma unroll
        for (int r = 0; r < 8; r++) {
            float cmin = 3.4e38f;
#pragma unroll
            for (int v = 0; v < 4; v++) {
                sv[r][v] = fmaf(c32[r][v], SINV, zn[r]);
                cmin = fminf(cmin, sv[r][v]);
            }
#pragma unroll
            for (int o = 16; o; o >>= 1)
                cmin = fminf(cmin, __shfl_xor_sync(0xffffffffu, cmin, o));
            rm[r] = fminf(rm[r], cmin);
        }
#pragma unroll
        for (int r = 0; r < 8; r++) {
            const int row = rg * 8 + r;
            const float thr = rm[r] + MARGIN;
#pragma unroll
            for (int v = 0; v < 4; v++) {
                if (sv[r][v] < thr) {
                    int sl = atomicAdd(&scnt[row], 1);
                    if (sl < CAPM) slist[row * CAPM + sl] = kb + v;
                }
            }
        }

        __syncthreads();
    }

    if (tid < NRB) {
        int cnt = scnt[tid];
        int n = n0 + tid;
        g_cand_cnt[n] = (cnt > CAPM) ? (CAPM + 1) : cnt;
        int m = (cnt < CAPM) ? cnt : CAPM;
        for (int j = 0; j < m; j++) g_cand[n * CAPM + j] = slist[tid * CAPM + j];
    }
}

// ---------------------------------------------------------------------------
// Kernel 4: exact rescue, WARP-PER-ROW (validated 1.4us in R15; bit-exact
// sequential fp32 chain + lexicographic (val, idx) min via shfl).
// Defensive clamp: a sentinel winner (empty list) maps to index 0 instead
// of an OOB gather.
// ---------------------------------------------------------------------------
__global__ __launch_bounds__(256)
void rescue_kernel(float* __restrict__ idxf) {
    __shared__ __align__(16) float zs[8][DD];
    const int tid = threadIdx.x;
    const int w = tid >> 5, lane = tid & 31;
    const int n0 = blockIdx.x * 8;
    const int n = n0 + w;

    for (int i = tid; i < 8 * 64; i += 256) {
        int r = i >> 6, seg = i & 63;
        *(float4*)&zs[r][seg * 4] = *(const float4*)&g_zf[(n0 + r) * DD + seg * 4];
    }
    __syncthreads();

    const float zn = g_zn[n];
    const int cnt = g_cand_cnt[n];
    const float4* zr = (const float4*)zs[w];

    float bv = 3.4e38f; int bi = 0x7FFFFFFF;
    if (cnt > CAPM) {
        for (int k = lane; k < KC; k += 32) {
            float acc = 0.f;
            const float4* cb = (const float4*)&g_codebook[k * DD];
#pragma unroll 4
            for (int d4 = 0; d4 < 64; d4++) {
                float4 cc = cb[d4];
                float4 zv = zr[d4];
                acc = fmaf(zv.x, cc.x, acc); acc = fmaf(zv.y, cc.y, acc);
                acc = fmaf(zv.z, cc.z, acc); acc = fmaf(zv.w, cc.w, acc);
            }
            float s = fmaf(-2.f, acc, zn);
            if (s < bv || (s == bv && k < bi)) { bv = s; bi = k; }
        }
    } else if (lane < cnt) {
        int k = g_cand[n * CAPM + lane];
        float acc = 0.f;
        const float4* cb = (const float4*)&g_codebook[k * DD];
#pragma unroll 4
        for (int d4 = 0; d4 < 64; d4++) {
            float4 cc = cb[d4];
            float4 zv = zr[d4];
            acc = fmaf(zv.x, cc.x, acc); acc = fmaf(zv.y, cc.y, acc);
            acc = fmaf(zv.z, cc.z, acc); acc = fmaf(zv.w, cc.w, acc);
        }
        bv = fmaf(-2.f, acc, zn);
        bi = k;
    }

#pragma unroll
    for (int o = 16; o; o >>= 1) {
        float v = __shfl_xor_sync(0xffffffffu, bv, o);
        int i2 = __shfl_xor_sync(0xffffffffu, bi, o);
        if (v < bv || (v == bv && i2 < bi)) { bv = v; bi = i2; }
    }
    if (lane == 0) {
        int safe = (bi >= 0 && bi < KC) ? bi : 0;   // defensive clamp
        g_minidx[n] = safe;
        if (idxf) idxf[n] = (float)safe;
    }
}

// ---------------------------------------------------------------------------
// Kernel 5: gather + straight-through output + squared error partials.
// out = fl(zt + fl(zq - zt)) exactly as the reference.
// ---------------------------------------------------------------------------
__global__ void gather_out(const float* __restrict__ z, float* __restrict__ out) {
    __shared__ float s[256 * 33];
    const int tid = threadIdx.x;
    const int n0 = blockIdx.x * 32;
    const int b = n0 >> 10, hw0 = n0 & 1023;

#pragma unroll 1
    for (int nl = 0; nl < 32; nl++) {
        int ci = g_minidx[n0 + nl];
        s[tid * 33 + nl] = g_codebook[ci * DD + tid];
    }
    __syncthreads();

    float local = 0.f;
    const float* zb = z + b * CHW + hw0;
    float* ob = out + b * CHW + hw0;
    for (int e = tid; e < 32 * DD; e += 256) {
        int c = e >> 5, hl = e & 31;
        float q  = s[c * 33 + hl];
        float zv = zb[c * HW + hl];
        float d  = q - zv;
        ob[c * HW + hl] = zv + d;
        local = fmaf(d, d, local);
    }
    __syncthreads();
    float* red = s;
    red[tid] = local;
    __syncthreads();
    for (int o = 128; o; o >>= 1) {
        if (tid < o) red[tid] += red[tid + o];
        __syncthreads();
    }
    if (tid == 0) g_partials[blockIdx.x] = red[0];
}

// ---------------------------------------------------------------------------
// Kernel 6: final reduction + loss scalars
// ---------------------------------------------------------------------------
__global__ void finalize_kernel(float* __restrict__ outp, int has_scalars) {
    __shared__ float red[512];
    const int tid = threadIdx.x;
    red[tid] = g_partials[tid];
    __syncthreads();
    for (int o = 256; o; o >>= 1) {
        if (tid < o) red[tid] += red[tid + o];
        __syncthreads();
    }
    if (tid == 0 && has_scalars) {
        float mse = red[0] * (1.0f / 4194304.0f);
        float cl  = 0.25f * mse;
        float bl  = mse;
        outp[4194304] = cl + bl;
        outp[4194305] = cl;
        outp[4194306] = bl;
    }
}

// ---------------------------------------------------------------------------
extern "C" void kernel_launch(void* const* d_in, const int* in_sizes, int n_in,
                              void* d_out, int out_size) {
    const float* z   = (const float*)d_in[0];   // [16,256,32,32]
    const float* emb = (const float*)d_in[1];   // [8192,256]
    const float* pw  = (const float*)d_in[2];   // [256,256]
    float* out = (float*)d_out;

    cudaFuncSetAttribute(argmin_h2,
                         cudaFuncAttributeMaxDynamicSharedMemorySize, SMEM_H2);

    codebook_gemm<<<dim3(4, 128), 256>>>(emb, pw);
    z_prep<<<512, 256>>>(z);

    float* idxf = nullptr;
    if (out_size >= 4194307 + NR) idxf = out + 4194307;

    argmin_h2<<<NR / NRB, 512, SMEM_H2>>>();
    rescue_kernel<<<NR / 8, 256>>>(idxf);
    gather_out<<<512, 256>>>(z, out);
    finalize_kernel<<<1, 512>>>(out, (out_size >= 4194307) ? 1 : 0);
}